// round 6
// baseline (speedup 1.0000x reference)
#include <cuda_runtime.h>
#include <cuda_bf16.h>
#include <cstdint>
#include <cstddef>

#define NB 4
#define NH 16
#define NS 2048
#define ND 64
#define KPAD 72

static __device__ __forceinline__ uint32_t sptr(const void* p) {
    return (uint32_t)__cvta_generic_to_shared(p);
}
static __device__ __forceinline__ void ldsm4(uint32_t& r0, uint32_t& r1, uint32_t& r2, uint32_t& r3, uint32_t a) {
    asm volatile("ldmatrix.sync.aligned.m8n8.x4.shared.b16 {%0,%1,%2,%3},[%4];"
                 : "=r"(r0), "=r"(r1), "=r"(r2), "=r"(r3) : "r"(a));
}
static __device__ __forceinline__ void ldsm4t(uint32_t& r0, uint32_t& r1, uint32_t& r2, uint32_t& r3, uint32_t a) {
    asm volatile("ldmatrix.sync.aligned.m8n8.x4.trans.shared.b16 {%0,%1,%2,%3},[%4];"
                 : "=r"(r0), "=r"(r1), "=r"(r2), "=r"(r3) : "r"(a));
}
static __device__ __forceinline__ void mma16816(float* d, const uint32_t* a, uint32_t b0, uint32_t b1) {
    asm volatile(
        "mma.sync.aligned.m16n8k16.row.col.f32.bf16.bf16.f32 "
        "{%0,%1,%2,%3},{%4,%5,%6,%7},{%8,%9},{%0,%1,%2,%3};"
        : "+f"(d[0]), "+f"(d[1]), "+f"(d[2]), "+f"(d[3])
        : "r"(a[0]), "r"(a[1]), "r"(a[2]), "r"(a[3]), "r"(b0), "r"(b1));
}
static __device__ __forceinline__ void split_pack(float a, float b, uint32_t& hi, uint32_t& lo) {
    __nv_bfloat16 ha = __float2bfloat16(a);
    __nv_bfloat16 hb = __float2bfloat16(b);
    float la = a - __bfloat162float(ha);
    float lb = b - __bfloat162float(hb);
    __nv_bfloat162 h; h.x = ha; h.y = hb;
    __nv_bfloat162 l; l.x = __float2bfloat16(la); l.y = __float2bfloat16(lb);
    hi = *(uint32_t*)&h;
    lo = *(uint32_t*)&l;
}
static __device__ __forceinline__ void split_store4(__nv_bfloat16* hi, __nv_bfloat16* lo, float4 v) {
    __nv_bfloat16 h0 = __float2bfloat16(v.x), h1 = __float2bfloat16(v.y);
    __nv_bfloat16 h2 = __float2bfloat16(v.z), h3 = __float2bfloat16(v.w);
    float l0 = v.x - __bfloat162float(h0), l1 = v.y - __bfloat162float(h1);
    float l2 = v.z - __bfloat162float(h2), l3 = v.w - __bfloat162float(h3);
    __nv_bfloat162 p;
    p.x = h0; p.y = h1; ((__nv_bfloat162*)hi)[0] = p;
    p.x = h2; p.y = h3; ((__nv_bfloat162*)hi)[1] = p;
    p.x = __float2bfloat16(l0); p.y = __float2bfloat16(l1); ((__nv_bfloat162*)lo)[0] = p;
    p.x = __float2bfloat16(l2); p.y = __float2bfloat16(l3); ((__nv_bfloat162*)lo)[1] = p;
}

// Fused two-loop attention:
//   loop1: Z[row] = sum exp(qk/8) over causal band (K staged only)
//   loop2: recompute s, write P = exp(s)/Z once (normalized), accumulate O = P V
// grid(64, 16), block 256, 2 CTAs/SM.
__global__ __launch_bounds__(256, 2) void attn_fused(const float* __restrict__ Q,
                                                     const float* __restrict__ K,
                                                     const float* __restrict__ V,
                                                     float* __restrict__ ctx,
                                                     float* __restrict__ attn) {
    extern __shared__ char smem[];
    float* qs = (float*)smem;                            // 128x64 fp32
    __nv_bfloat16* khi = (__nv_bfloat16*)(smem + 32768); // 64 x KPAD each
    __nv_bfloat16* klo = khi + 64 * KPAD;
    __nv_bfloat16* vhi = klo + 64 * KPAD;
    __nv_bfloat16* vlo = vhi + 64 * KPAD;

    const int bh = blockIdx.x;
    const int qt = (int)gridDim.y - 1 - (int)blockIdx.y;  // heavy tiles first
    const int r0 = qt << 7;
    const float* Qb = Q + ((size_t)bh * NS + r0) * ND;
    const float* Kb = K + (size_t)bh * NS * ND;
    const float* Vb = V + (size_t)bh * NS * ND;
    const int tid = threadIdx.x;

    for (int i = tid; i < 2048; i += 256) {
        float4 v = ((const float4*)Qb)[i];
        v.x *= 0.125f; v.y *= 0.125f; v.z *= 0.125f; v.w *= 0.125f;
        ((float4*)qs)[i] = v;
    }
    __syncthreads();

    const int w = tid >> 5, L = tid & 31, g2 = L >> 2, t4 = L & 3, g3 = L >> 3, lr = L & 7;

    uint32_t Ah[4][4], Al[4][4];
    {
        const int rA = (w << 4) + g2;
#pragma unroll
        for (int kc = 0; kc < 4; kc++) {
            int c0 = (kc << 4) + (t4 << 1);
            split_pack(qs[rA * 64 + c0],           qs[rA * 64 + c0 + 1],           Ah[kc][0], Al[kc][0]);
            split_pack(qs[(rA + 8) * 64 + c0],     qs[(rA + 8) * 64 + c0 + 1],     Ah[kc][1], Al[kc][1]);
            split_pack(qs[rA * 64 + c0 + 8],       qs[rA * 64 + c0 + 9],           Ah[kc][2], Al[kc][2]);
            split_pack(qs[(rA + 8) * 64 + c0 + 8], qs[(rA + 8) * 64 + c0 + 9],     Ah[kc][3], Al[kc][3]);
        }
    }

    const int row0 = r0 + (w << 4) + g2;
    const int row1 = row0 + 8;
    const int key_l = lr + ((g3 & 1) << 3);
    const int d_l = (g3 & 2) << 2;
    const int nsteps = (r0 + 128) >> 6;

    // ---------------- loop 1: Z only (K staged, no V, no stores) --------------
    float zs0 = 0.f, zs1 = 0.f;
    for (int s = 0; s < nsteps; s++) {
        const int k0 = s << 6;
        __syncthreads();
        for (int i = tid; i < 1024; i += 256) {
            int key = i >> 4, d = (i & 15) << 2;
            float4 vk = ((const float4*)(Kb + (size_t)k0 * ND))[i];
            split_store4(khi + key * KPAD + d, klo + key * KPAD + d, vk);
        }
        __syncthreads();

#pragma unroll
        for (int np = 0; np < 4; np++) {
            float Sv[8] = {0.f, 0.f, 0.f, 0.f, 0.f, 0.f, 0.f, 0.f};
#pragma unroll
            for (int kc = 0; kc < 4; kc++) {
                uint32_t b0, b1, b2, b3, c0, c1, c2, c3;
                uint32_t off = (uint32_t)((np * 16 + key_l) * KPAD + (kc << 4) + d_l);
                ldsm4(b0, b1, b2, b3, sptr(khi + off));
                ldsm4(c0, c1, c2, c3, sptr(klo + off));
                mma16816(Sv,     Ah[kc], b0, b2);
                mma16816(Sv,     Al[kc], b0, b2);
                mma16816(Sv,     Ah[kc], c0, c2);
                mma16816(Sv + 4, Ah[kc], b1, b3);
                mma16816(Sv + 4, Al[kc], b1, b3);
                mma16816(Sv + 4, Ah[kc], c1, c3);
            }
            const int kb = k0 + (np << 4) + (t4 << 1);
            float p;
            p = (kb     <= row0) ? __expf(Sv[0]) : 0.f; zs0 += p;
            p = (kb + 1 <= row0) ? __expf(Sv[1]) : 0.f; zs0 += p;
            p = (kb     <= row1) ? __expf(Sv[2]) : 0.f; zs1 += p;
            p = (kb + 1 <= row1) ? __expf(Sv[3]) : 0.f; zs1 += p;
            p = (kb + 8 <= row0) ? __expf(Sv[4]) : 0.f; zs0 += p;
            p = (kb + 9 <= row0) ? __expf(Sv[5]) : 0.f; zs0 += p;
            p = (kb + 8 <= row1) ? __expf(Sv[6]) : 0.f; zs1 += p;
            p = (kb + 9 <= row1) ? __expf(Sv[7]) : 0.f; zs1 += p;
        }
    }

    zs0 += __shfl_xor_sync(0xffffffffu, zs0, 1);
    zs0 += __shfl_xor_sync(0xffffffffu, zs0, 2);
    zs1 += __shfl_xor_sync(0xffffffffu, zs1, 1);
    zs1 += __shfl_xor_sync(0xffffffffu, zs1, 2);
    const float zi0 = 1.0f / zs0;
    const float zi1 = 1.0f / zs1;

    float* arow0 = attn + ((size_t)bh * NS + row0) * NS;
    float* arow1 = attn + ((size_t)bh * NS + row1) * NS;

    float Ov[8][4];
#pragma unroll
    for (int i = 0; i < 8; i++)
#pragma unroll
        for (int j = 0; j < 4; j++) Ov[i][j] = 0.f;

    // ---------------- loop 2: emit normalized P, accumulate O ----------------
    for (int s = 0; s < nsteps; s++) {
        const int k0 = s << 6;
        __syncthreads();
        for (int i = tid; i < 1024; i += 256) {
            int key = i >> 4, d = (i & 15) << 2;
            float4 vk = ((const float4*)(Kb + (size_t)k0 * ND))[i];
            split_store4(khi + key * KPAD + d, klo + key * KPAD + d, vk);
            float4 vv = ((const float4*)(Vb + (size_t)k0 * ND))[i];
            split_store4(vhi + key * KPAD + d, vlo + key * KPAD + d, vv);
        }
        __syncthreads();

#pragma unroll
        for (int np = 0; np < 4; np++) {
            float Sv[8] = {0.f, 0.f, 0.f, 0.f, 0.f, 0.f, 0.f, 0.f};
#pragma unroll
            for (int kc = 0; kc < 4; kc++) {
                uint32_t b0, b1, b2, b3, c0, c1, c2, c3;
                uint32_t off = (uint32_t)((np * 16 + key_l) * KPAD + (kc << 4) + d_l);
                ldsm4(b0, b1, b2, b3, sptr(khi + off));
                ldsm4(c0, c1, c2, c3, sptr(klo + off));
                mma16816(Sv,     Ah[kc], b0, b2);
                mma16816(Sv,     Al[kc], b0, b2);
                mma16816(Sv,     Ah[kc], c0, c2);
                mma16816(Sv + 4, Ah[kc], b1, b3);
                mma16816(Sv + 4, Al[kc], b1, b3);
                mma16816(Sv + 4, Ah[kc], c1, c3);
            }
            const int kb = k0 + (np << 4) + (t4 << 1);
            // normalized probabilities
            float p0 = (kb     <= row0) ? __expf(Sv[0]) * zi0 : 0.f;
            float p1 = (kb + 1 <= row0) ? __expf(Sv[1]) * zi0 : 0.f;
            float p2 = (kb     <= row1) ? __expf(Sv[2]) * zi1 : 0.f;
            float p3 = (kb + 1 <= row1) ? __expf(Sv[3]) * zi1 : 0.f;
            float p4 = (kb + 8 <= row0) ? __expf(Sv[4]) * zi0 : 0.f;
            float p5 = (kb + 9 <= row0) ? __expf(Sv[5]) * zi0 : 0.f;
            float p6 = (kb + 8 <= row1) ? __expf(Sv[6]) * zi1 : 0.f;
            float p7 = (kb + 9 <= row1) ? __expf(Sv[7]) * zi1 : 0.f;

            *(float2*)(arow0 + kb)     = make_float2(p0, p1);
            *(float2*)(arow1 + kb)     = make_float2(p2, p3);
            *(float2*)(arow0 + kb + 8) = make_float2(p4, p5);
            *(float2*)(arow1 + kb + 8) = make_float2(p6, p7);

            uint32_t Ph[4], Pl[4];
            split_pack(p0, p1, Ph[0], Pl[0]);
            split_pack(p2, p3, Ph[1], Pl[1]);
            split_pack(p4, p5, Ph[2], Pl[2]);
            split_pack(p6, p7, Ph[3], Pl[3]);

#pragma unroll
            for (int dd = 0; dd < 4; dd++) {
                uint32_t v0, v1, v2, v3, u0, u1, u2, u3;
                uint32_t off = (uint32_t)((np * 16 + key_l) * KPAD + (dd << 4) + d_l);
                ldsm4t(v0, v1, v2, v3, sptr(vhi + off));
                ldsm4t(u0, u1, u2, u3, sptr(vlo + off));
                mma16816(Ov[2 * dd],     Ph, v0, v1);
                mma16816(Ov[2 * dd],     Pl, v0, v1);
                mma16816(Ov[2 * dd],     Ph, u0, u1);
                mma16816(Ov[2 * dd + 1], Ph, v2, v3);
                mma16816(Ov[2 * dd + 1], Pl, v2, v3);
                mma16816(Ov[2 * dd + 1], Ph, u2, u3);
            }
        }
    }

    // write context (P already normalized, no scaling needed)
    {
        float* crow0 = ctx + ((size_t)bh * NS + row0) * ND;
        float* crow1 = ctx + ((size_t)bh * NS + row1) * ND;
#pragma unroll
        for (int dt = 0; dt < 8; dt++) {
            int c = (dt << 3) + (t4 << 1);
            *(float2*)(crow0 + c) = make_float2(Ov[dt][0], Ov[dt][1]);
            *(float2*)(crow1 + c) = make_float2(Ov[dt][2], Ov[dt][3]);
        }
    }

    // zero-fill masked region beyond the causal band
    {
        const int ks = (qt + 1) << 7;
        if (ks < NS) {
            const int width4 = (NS - ks) >> 2;
            float4 z4 = make_float4(0.f, 0.f, 0.f, 0.f);
            float* abase = attn + ((size_t)bh * NS + r0) * NS + ks;
            const int total = 128 * width4;
            for (int i = tid; i < total; i += 256) {
                int row = i / width4;
                int c = i - row * width4;
                ((float4*)(abase + (size_t)row * NS))[c] = z4;
            }
        }
    }
}

extern "C" void kernel_launch(void* const* d_in, const int* in_sizes, int n_in,
                              void* d_out, int out_size) {
    const float* Q = (const float*)d_in[0];
    const float* K = (const float*)d_in[1];
    const float* V = (const float*)d_in[2];
    float* ctx = (float*)d_out;
    float* attn = (float*)d_out + (size_t)NB * NH * NS * ND;

    static bool attr_set = false;
    if (!attr_set) {
        cudaFuncSetAttribute(attn_fused, cudaFuncAttributeMaxDynamicSharedMemorySize, 69632);
        attr_set = true;
    }

    dim3 grid(NB * NH, NS / 128);
    dim3 block(256);
    attn_fused<<<grid, block, 69632>>>(Q, K, V, ctx, attn);
}

// round 7
// speedup vs baseline: 1.1089x; 1.1089x over previous
#include <cuda_runtime.h>
#include <cuda_bf16.h>
#include <cstdint>
#include <cstddef>

#define NB 4
#define NH 16
#define NS 2048
#define ND 64
#define KPAD 72
#define STAGE_OFF 36864   // after 4 bf16 buffers of 64*KPAD*2 = 9216 B each

static __device__ __forceinline__ uint32_t sptr(const void* p) {
    return (uint32_t)__cvta_generic_to_shared(p);
}
static __device__ __forceinline__ void cpasync16(uint32_t dst, const void* src) {
    asm volatile("cp.async.cg.shared.global [%0], [%1], 16;" :: "r"(dst), "l"(src));
}
static __device__ __forceinline__ void ldsm4(uint32_t& r0, uint32_t& r1, uint32_t& r2, uint32_t& r3, uint32_t a) {
    asm volatile("ldmatrix.sync.aligned.m8n8.x4.shared.b16 {%0,%1,%2,%3},[%4];"
                 : "=r"(r0), "=r"(r1), "=r"(r2), "=r"(r3) : "r"(a));
}
static __device__ __forceinline__ void ldsm4t(uint32_t& r0, uint32_t& r1, uint32_t& r2, uint32_t& r3, uint32_t a) {
    asm volatile("ldmatrix.sync.aligned.m8n8.x4.trans.shared.b16 {%0,%1,%2,%3},[%4];"
                 : "=r"(r0), "=r"(r1), "=r"(r2), "=r"(r3) : "r"(a));
}
static __device__ __forceinline__ void mma16816(float* d, const uint32_t* a, uint32_t b0, uint32_t b1) {
    asm volatile(
        "mma.sync.aligned.m16n8k16.row.col.f32.bf16.bf16.f32 "
        "{%0,%1,%2,%3},{%4,%5,%6,%7},{%8,%9},{%0,%1,%2,%3};"
        : "+f"(d[0]), "+f"(d[1]), "+f"(d[2]), "+f"(d[3])
        : "r"(a[0]), "r"(a[1]), "r"(a[2]), "r"(a[3]), "r"(b0), "r"(b1));
}
static __device__ __forceinline__ void split_pack(float a, float b, uint32_t& hi, uint32_t& lo) {
    __nv_bfloat16 ha = __float2bfloat16(a);
    __nv_bfloat16 hb = __float2bfloat16(b);
    float la = a - __bfloat162float(ha);
    float lb = b - __bfloat162float(hb);
    __nv_bfloat162 h; h.x = ha; h.y = hb;
    __nv_bfloat162 l; l.x = __float2bfloat16(la); l.y = __float2bfloat16(lb);
    hi = *(uint32_t*)&h;
    lo = *(uint32_t*)&l;
}
static __device__ __forceinline__ void split_store4(__nv_bfloat16* hi, __nv_bfloat16* lo, float4 v) {
    __nv_bfloat16 h0 = __float2bfloat16(v.x), h1 = __float2bfloat16(v.y);
    __nv_bfloat16 h2 = __float2bfloat16(v.z), h3 = __float2bfloat16(v.w);
    float l0 = v.x - __bfloat162float(h0), l1 = v.y - __bfloat162float(h1);
    float l2 = v.z - __bfloat162float(h2), l3 = v.w - __bfloat162float(h3);
    __nv_bfloat162 p;
    p.x = h0; p.y = h1; ((__nv_bfloat162*)hi)[0] = p;
    p.x = h2; p.y = h3; ((__nv_bfloat162*)hi)[1] = p;
    p.x = __float2bfloat16(l0); p.y = __float2bfloat16(l1); ((__nv_bfloat162*)lo)[0] = p;
    p.x = __float2bfloat16(l2); p.y = __float2bfloat16(l3); ((__nv_bfloat162*)lo)[1] = p;
}

// Single-loop fused attention (R4 math) + cp.async double-buffered K/V staging.
// P written unnormalized, Z accumulated in-warp, O normalized at epilogue,
// attn rows rescaled in place by 1/Z, masked region zero-filled.
// grid(64, 16), block 256, 2 CTAs/SM.
__global__ __launch_bounds__(256, 2) void attn_fused(const float* __restrict__ Q,
                                                     const float* __restrict__ K,
                                                     const float* __restrict__ V,
                                                     float* __restrict__ ctx,
                                                     float* __restrict__ attn) {
    extern __shared__ char smem[];
    __nv_bfloat16* khi = (__nv_bfloat16*)smem;           // 64 x KPAD each
    __nv_bfloat16* klo = khi + 64 * KPAD;
    __nv_bfloat16* vhi = klo + 64 * KPAD;
    __nv_bfloat16* vlo = vhi + 64 * KPAD;
    // two fp32 staging buffers of 32KB (K tile 16KB + V tile 16KB) at STAGE_OFF
    // qs (128x64 fp32, 32KB) overlays staging buffer 1; freed after A-frag build
    float* qs = (float*)(smem + STAGE_OFF + 32768);
    const uint32_t stage_base = sptr(smem + STAGE_OFF);

    const int bh = blockIdx.x;
    const int qt = (int)gridDim.y - 1 - (int)blockIdx.y;  // heavy tiles first
    const int r0 = qt << 7;
    const float* Qb = Q + ((size_t)bh * NS + r0) * ND;
    const float* Kb = K + (size_t)bh * NS * ND;
    const float* Vb = V + (size_t)bh * NS * ND;
    const int tid = threadIdx.x;
    const int nsteps = (r0 + 128) >> 6;

    // load Q (scaled) into qs, and concurrently prefetch K/V tile 0 into buffer 0
    for (int i = tid; i < 2048; i += 256) {
        float4 v = ((const float4*)Qb)[i];
        v.x *= 0.125f; v.y *= 0.125f; v.z *= 0.125f; v.w *= 0.125f;
        ((float4*)qs)[i] = v;
    }
    {
        const float4* kg = (const float4*)Kb;
        const float4* vg = (const float4*)Vb;
        for (int i = tid; i < 1024; i += 256) {
            cpasync16(stage_base + i * 16, kg + i);
            cpasync16(stage_base + 16384 + i * 16, vg + i);
        }
        asm volatile("cp.async.commit_group;");
    }
    __syncthreads();

    const int w = tid >> 5, L = tid & 31, g2 = L >> 2, t4 = L & 3, g3 = L >> 3, lr = L & 7;

    uint32_t Ah[4][4], Al[4][4];
    {
        const int rA = (w << 4) + g2;
#pragma unroll
        for (int kc = 0; kc < 4; kc++) {
            int c0 = (kc << 4) + (t4 << 1);
            split_pack(qs[rA * 64 + c0],           qs[rA * 64 + c0 + 1],           Ah[kc][0], Al[kc][0]);
            split_pack(qs[(rA + 8) * 64 + c0],     qs[(rA + 8) * 64 + c0 + 1],     Ah[kc][1], Al[kc][1]);
            split_pack(qs[rA * 64 + c0 + 8],       qs[rA * 64 + c0 + 9],           Ah[kc][2], Al[kc][2]);
            split_pack(qs[(rA + 8) * 64 + c0 + 8], qs[(rA + 8) * 64 + c0 + 9],     Ah[kc][3], Al[kc][3]);
        }
    }
    __syncthreads();  // qs fully consumed; buffer 1 may now be overwritten

    const int row0 = r0 + (w << 4) + g2;
    const int row1 = row0 + 8;
    const int key_l = lr + ((g3 & 1) << 3);
    const int d_l = (g3 & 2) << 2;

    float* arow0 = attn + ((size_t)bh * NS + row0) * NS;
    float* arow1 = attn + ((size_t)bh * NS + row1) * NS;

    float zs0 = 0.f, zs1 = 0.f;
    float Ov[8][4];
#pragma unroll
    for (int i = 0; i < 8; i++)
#pragma unroll
        for (int j = 0; j < 4; j++) Ov[i][j] = 0.f;

    for (int s = 0; s < nsteps; s++) {
        // prefetch next tile into the other buffer, then wait for tile s
        if (s + 1 < nsteps) {
            const int k1 = (s + 1) << 6;
            const uint32_t sb = stage_base + ((s + 1) & 1) * 32768;
            const float4* kg = (const float4*)(Kb + (size_t)k1 * ND);
            const float4* vg = (const float4*)(Vb + (size_t)k1 * ND);
            for (int i = tid; i < 1024; i += 256) {
                cpasync16(sb + i * 16, kg + i);
                cpasync16(sb + 16384 + i * 16, vg + i);
            }
            asm volatile("cp.async.commit_group;");
            asm volatile("cp.async.wait_group 1;");
        } else {
            asm volatile("cp.async.wait_group 0;");
        }
        __syncthreads();  // tile s visible to all; previous compute done

        // convert fp32 staged tile -> bf16 hi/lo buffers
        {
            const float4* kf = (const float4*)(smem + STAGE_OFF + (s & 1) * 32768);
            const float4* vf = kf + 1024;
            for (int i = tid; i < 1024; i += 256) {
                int key = i >> 4, d = (i & 15) << 2;
                split_store4(khi + key * KPAD + d, klo + key * KPAD + d, kf[i]);
                split_store4(vhi + key * KPAD + d, vlo + key * KPAD + d, vf[i]);
            }
        }
        __syncthreads();

        const int k0 = s << 6;
#pragma unroll
        for (int np = 0; np < 4; np++) {
            float Sv[8] = {0.f, 0.f, 0.f, 0.f, 0.f, 0.f, 0.f, 0.f};
#pragma unroll
            for (int kc = 0; kc < 4; kc++) {
                uint32_t b0, b1, b2, b3, c0, c1, c2, c3;
                uint32_t off = (uint32_t)((np * 16 + key_l) * KPAD + (kc << 4) + d_l);
                ldsm4(b0, b1, b2, b3, sptr(khi + off));
                ldsm4(c0, c1, c2, c3, sptr(klo + off));
                mma16816(Sv,     Ah[kc], b0, b2);
                mma16816(Sv,     Al[kc], b0, b2);
                mma16816(Sv,     Ah[kc], c0, c2);
                mma16816(Sv + 4, Ah[kc], b1, b3);
                mma16816(Sv + 4, Al[kc], b1, b3);
                mma16816(Sv + 4, Ah[kc], c1, c3);
            }
            const int kb = k0 + (np << 4) + (t4 << 1);
            // unnormalized probabilities (Z divided out later)
            float p0 = (kb     <= row0) ? __expf(Sv[0]) : 0.f;
            float p1 = (kb + 1 <= row0) ? __expf(Sv[1]) : 0.f;
            float p2 = (kb     <= row1) ? __expf(Sv[2]) : 0.f;
            float p3 = (kb + 1 <= row1) ? __expf(Sv[3]) : 0.f;
            float p4 = (kb + 8 <= row0) ? __expf(Sv[4]) : 0.f;
            float p5 = (kb + 9 <= row0) ? __expf(Sv[5]) : 0.f;
            float p6 = (kb + 8 <= row1) ? __expf(Sv[6]) : 0.f;
            float p7 = (kb + 9 <= row1) ? __expf(Sv[7]) : 0.f;
            zs0 += p0 + p1 + p4 + p5;
            zs1 += p2 + p3 + p6 + p7;

            *(float2*)(arow0 + kb)     = make_float2(p0, p1);
            *(float2*)(arow1 + kb)     = make_float2(p2, p3);
            *(float2*)(arow0 + kb + 8) = make_float2(p4, p5);
            *(float2*)(arow1 + kb + 8) = make_float2(p6, p7);

            uint32_t Ph[4], Pl[4];
            split_pack(p0, p1, Ph[0], Pl[0]);
            split_pack(p2, p3, Ph[1], Pl[1]);
            split_pack(p4, p5, Ph[2], Pl[2]);
            split_pack(p6, p7, Ph[3], Pl[3]);

#pragma unroll
            for (int dd = 0; dd < 4; dd++) {
                uint32_t v0, v1, v2, v3, u0, u1, u2, u3;
                uint32_t off = (uint32_t)((np * 16 + key_l) * KPAD + (dd << 4) + d_l);
                ldsm4t(v0, v1, v2, v3, sptr(vhi + off));
                ldsm4t(u0, u1, u2, u3, sptr(vlo + off));
                mma16816(Ov[2 * dd],     Ph, v0, v1);
                mma16816(Ov[2 * dd],     Pl, v0, v1);
                mma16816(Ov[2 * dd],     Ph, u0, u1);
                mma16816(Ov[2 * dd + 1], Ph, v2, v3);
                mma16816(Ov[2 * dd + 1], Pl, v2, v3);
                mma16816(Ov[2 * dd + 1], Ph, u2, u3);
            }
        }
    }

    // reduce Z over the 4 lanes covering each row
    zs0 += __shfl_xor_sync(0xffffffffu, zs0, 1);
    zs0 += __shfl_xor_sync(0xffffffffu, zs0, 2);
    zs1 += __shfl_xor_sync(0xffffffffu, zs1, 1);
    zs1 += __shfl_xor_sync(0xffffffffu, zs1, 2);
    const float zi0 = 1.0f / zs0;
    const float zi1 = 1.0f / zs1;

    // write context, normalized
    {
        float* crow0 = ctx + ((size_t)bh * NS + row0) * ND;
        float* crow1 = ctx + ((size_t)bh * NS + row1) * ND;
#pragma unroll
        for (int dt = 0; dt < 8; dt++) {
            int c = (dt << 3) + (t4 << 1);
            *(float2*)(crow0 + c) = make_float2(Ov[dt][0] * zi0, Ov[dt][1] * zi0);
            *(float2*)(crow1 + c) = make_float2(Ov[dt][2] * zi1, Ov[dt][3] * zi1);
        }
    }

    // rescale the warp's 16 attn rows in place (reads mostly hit L2)
    __syncwarp();
    {
        const int ks = (qt + 1) << 7;       // causal band width for this q-tile
        const int n4 = ks >> 2;             // float4 per row
        float* wbase = attn + ((size_t)bh * NS + r0 + (w << 4)) * NS;
#pragma unroll 1
        for (int j = 0; j < 8; j++) {
            float za = __shfl_sync(0xffffffffu, zs0, j << 2);
            float zb = __shfl_sync(0xffffffffu, zs1, j << 2);
            float ra = 1.0f / za, rb = 1.0f / zb;
            float4* rowa = (float4*)(wbase + (size_t)j * NS);
            float4* rowb = (float4*)(wbase + (size_t)(j + 8) * NS);
            for (int c = L; c < n4; c += 32) {
                float4 v = rowa[c];
                v.x *= ra; v.y *= ra; v.z *= ra; v.w *= ra;
                rowa[c] = v;
                float4 u = rowb[c];
                u.x *= rb; u.y *= rb; u.z *= rb; u.w *= rb;
                rowb[c] = u;
            }
        }
    }

    // zero-fill masked region beyond the causal band
    {
        const int ks = (qt + 1) << 7;
        if (ks < NS) {
            const int width4 = (NS - ks) >> 2;
            float4 z4 = make_float4(0.f, 0.f, 0.f, 0.f);
            float* abase = attn + ((size_t)bh * NS + r0) * NS + ks;
            const int total = 128 * width4;
            for (int i = tid; i < total; i += 256) {
                int row = i / width4;
                int c = i - row * width4;
                ((float4*)(abase + (size_t)row * NS))[c] = z4;
            }
        }
    }
}

extern "C" void kernel_launch(void* const* d_in, const int* in_sizes, int n_in,
                              void* d_out, int out_size) {
    const float* Q = (const float*)d_in[0];
    const float* K = (const float*)d_in[1];
    const float* V = (const float*)d_in[2];
    float* ctx = (float*)d_out;
    float* attn = (float*)d_out + (size_t)NB * NH * NS * ND;

    static bool attr_set = false;
    if (!attr_set) {
        cudaFuncSetAttribute(attn_fused, cudaFuncAttributeMaxDynamicSharedMemorySize, 102400);
        attr_set = true;
    }

    dim3 grid(NB * NH, NS / 128);
    dim3 block(256);
    attn_fused<<<grid, block, 102400>>>(Q, K, V, ctx, attn);
}

// round 8
// speedup vs baseline: 1.3846x; 1.2487x over previous
#include <cuda_runtime.h>
#include <cuda_fp16.h>
#include <cstdint>
#include <cstddef>

#define NB 4
#define NH 16
#define NS 2048
#define ND 64
#define KPAD 72
#define STAGE_OFF 18432   // after 2 fp16 buffers of 64*KPAD*2 = 9216 B each

static __device__ __forceinline__ uint32_t sptr(const void* p) {
    return (uint32_t)__cvta_generic_to_shared(p);
}
static __device__ __forceinline__ void cpasync16(uint32_t dst, const void* src) {
    asm volatile("cp.async.cg.shared.global [%0], [%1], 16;" :: "r"(dst), "l"(src));
}
static __device__ __forceinline__ void ldsm4(uint32_t& r0, uint32_t& r1, uint32_t& r2, uint32_t& r3, uint32_t a) {
    asm volatile("ldmatrix.sync.aligned.m8n8.x4.shared.b16 {%0,%1,%2,%3},[%4];"
                 : "=r"(r0), "=r"(r1), "=r"(r2), "=r"(r3) : "r"(a));
}
static __device__ __forceinline__ void ldsm4t(uint32_t& r0, uint32_t& r1, uint32_t& r2, uint32_t& r3, uint32_t a) {
    asm volatile("ldmatrix.sync.aligned.m8n8.x4.trans.shared.b16 {%0,%1,%2,%3},[%4];"
                 : "=r"(r0), "=r"(r1), "=r"(r2), "=r"(r3) : "r"(a));
}
static __device__ __forceinline__ void mma16816(float* d, const uint32_t* a, uint32_t b0, uint32_t b1) {
    asm volatile(
        "mma.sync.aligned.m16n8k16.row.col.f32.f16.f16.f32 "
        "{%0,%1,%2,%3},{%4,%5,%6,%7},{%8,%9},{%0,%1,%2,%3};"
        : "+f"(d[0]), "+f"(d[1]), "+f"(d[2]), "+f"(d[3])
        : "r"(a[0]), "r"(a[1]), "r"(a[2]), "r"(a[3]), "r"(b0), "r"(b1));
}
// split pair of fp32 into fp16 hi + fp16 residual (packed half2 regs)
static __device__ __forceinline__ void split_pack(float a, float b, uint32_t& hi, uint32_t& lo) {
    __half ha = __float2half_rn(a);
    __half hb = __float2half_rn(b);
    float la = a - __half2float(ha);
    float lb = b - __half2float(hb);
    __half2 h = __halves2half2(ha, hb);
    __half2 l = __halves2half2(__float2half_rn(la), __float2half_rn(lb));
    hi = *(uint32_t*)&h;
    lo = *(uint32_t*)&l;
}
// fp32x4 -> fp16x4 store (hi only; residual term dropped by design)
static __device__ __forceinline__ void h4store(__half* dst, float4 v) {
    __half2 a = __halves2half2(__float2half_rn(v.x), __float2half_rn(v.y));
    __half2 b = __halves2half2(__float2half_rn(v.z), __float2half_rn(v.w));
    ((__half2*)dst)[0] = a;
    ((__half2*)dst)[1] = b;
}

// Fused attention, fp16 2-term split: S=(Qh+Ql)Kh, O=(Ph+Pl)Vh.
// P written unnormalized, Z in-warp, O normalized at epilogue, attn rows
// rescaled in place by 1/Z, masked region zero-filled.
// cp.async double-buffered K/V staging. grid(64,16), block 256, 2 CTAs/SM.
__global__ __launch_bounds__(256, 2) void attn_fused(const float* __restrict__ Q,
                                                     const float* __restrict__ K,
                                                     const float* __restrict__ V,
                                                     float* __restrict__ ctx,
                                                     float* __restrict__ attn) {
    extern __shared__ char smem[];
    __half* kh = (__half*)smem;                    // 64 x KPAD
    __half* vh = kh + 64 * KPAD;                   // 64 x KPAD
    // two fp32 staging buffers of 32KB (K 16KB + V 16KB) at STAGE_OFF
    // qs (128x64 fp32, 32KB) overlays staging buffer 1; freed after A-frag build
    float* qs = (float*)(smem + STAGE_OFF + 32768);
    const uint32_t stage_base = sptr(smem + STAGE_OFF);

    const int bh = blockIdx.x;
    const int qt = (int)gridDim.y - 1 - (int)blockIdx.y;  // heavy tiles first
    const int r0 = qt << 7;
    const float* Qb = Q + ((size_t)bh * NS + r0) * ND;
    const float* Kb = K + (size_t)bh * NS * ND;
    const float* Vb = V + (size_t)bh * NS * ND;
    const int tid = threadIdx.x;
    const int nsteps = (r0 + 128) >> 6;

    // load Q (scaled) into qs; prefetch K/V tile 0 into staging buffer 0
    for (int i = tid; i < 2048; i += 256) {
        float4 v = ((const float4*)Qb)[i];
        v.x *= 0.125f; v.y *= 0.125f; v.z *= 0.125f; v.w *= 0.125f;
        ((float4*)qs)[i] = v;
    }
    {
        const float4* kg = (const float4*)Kb;
        const float4* vg = (const float4*)Vb;
        for (int i = tid; i < 1024; i += 256) {
            cpasync16(stage_base + i * 16, kg + i);
            cpasync16(stage_base + 16384 + i * 16, vg + i);
        }
        asm volatile("cp.async.commit_group;");
    }
    __syncthreads();

    const int w = tid >> 5, L = tid & 31, g2 = L >> 2, t4 = L & 3, g3 = L >> 3, lr = L & 7;

    uint32_t Ah[4][4], Al[4][4];
    {
        const int rA = (w << 4) + g2;
#pragma unroll
        for (int kc = 0; kc < 4; kc++) {
            int c0 = (kc << 4) + (t4 << 1);
            split_pack(qs[rA * 64 + c0],           qs[rA * 64 + c0 + 1],           Ah[kc][0], Al[kc][0]);
            split_pack(qs[(rA + 8) * 64 + c0],     qs[(rA + 8) * 64 + c0 + 1],     Ah[kc][1], Al[kc][1]);
            split_pack(qs[rA * 64 + c0 + 8],       qs[rA * 64 + c0 + 9],           Ah[kc][2], Al[kc][2]);
            split_pack(qs[(rA + 8) * 64 + c0 + 8], qs[(rA + 8) * 64 + c0 + 9],     Ah[kc][3], Al[kc][3]);
        }
    }
    __syncthreads();  // qs consumed; staging buffer 1 may be overwritten

    const int row0 = r0 + (w << 4) + g2;
    const int row1 = row0 + 8;
    const int key_l = lr + ((g3 & 1) << 3);
    const int d_l = (g3 & 2) << 2;

    float* arow0 = attn + ((size_t)bh * NS + row0) * NS;
    float* arow1 = attn + ((size_t)bh * NS + row1) * NS;

    float zs0 = 0.f, zs1 = 0.f;
    float Ov[8][4];
#pragma unroll
    for (int i = 0; i < 8; i++)
#pragma unroll
        for (int j = 0; j < 4; j++) Ov[i][j] = 0.f;

    for (int s = 0; s < nsteps; s++) {
        // prefetch next tile into other buffer, then wait for tile s
        if (s + 1 < nsteps) {
            const int k1 = (s + 1) << 6;
            const uint32_t sb = stage_base + ((s + 1) & 1) * 32768;
            const float4* kg = (const float4*)(Kb + (size_t)k1 * ND);
            const float4* vg = (const float4*)(Vb + (size_t)k1 * ND);
            for (int i = tid; i < 1024; i += 256) {
                cpasync16(sb + i * 16, kg + i);
                cpasync16(sb + 16384 + i * 16, vg + i);
            }
            asm volatile("cp.async.commit_group;");
            asm volatile("cp.async.wait_group 1;");
        } else {
            asm volatile("cp.async.wait_group 0;");
        }
        __syncthreads();

        // convert staged fp32 -> fp16 (hi only)
        {
            const float4* kf = (const float4*)(smem + STAGE_OFF + (s & 1) * 32768);
            const float4* vf = kf + 1024;
            for (int i = tid; i < 1024; i += 256) {
                int key = i >> 4, d = (i & 15) << 2;
                h4store(kh + key * KPAD + d, kf[i]);
                h4store(vh + key * KPAD + d, vf[i]);
            }
        }
        __syncthreads();

        const int k0 = s << 6;
#pragma unroll
        for (int np = 0; np < 4; np++) {
            float Sv[8] = {0.f, 0.f, 0.f, 0.f, 0.f, 0.f, 0.f, 0.f};
#pragma unroll
            for (int kc = 0; kc < 4; kc++) {
                uint32_t b0, b1, b2, b3;
                uint32_t off = (uint32_t)((np * 16 + key_l) * KPAD + (kc << 4) + d_l);
                ldsm4(b0, b1, b2, b3, sptr(kh + off));
                mma16816(Sv,     Ah[kc], b0, b2);
                mma16816(Sv,     Al[kc], b0, b2);
                mma16816(Sv + 4, Ah[kc], b1, b3);
                mma16816(Sv + 4, Al[kc], b1, b3);
            }
            const int kb = k0 + (np << 4) + (t4 << 1);
            // unnormalized probabilities (Z divided out later)
            float p0 = (kb     <= row0) ? __expf(Sv[0]) : 0.f;
            float p1 = (kb + 1 <= row0) ? __expf(Sv[1]) : 0.f;
            float p2 = (kb     <= row1) ? __expf(Sv[2]) : 0.f;
            float p3 = (kb + 1 <= row1) ? __expf(Sv[3]) : 0.f;
            float p4 = (kb + 8 <= row0) ? __expf(Sv[4]) : 0.f;
            float p5 = (kb + 9 <= row0) ? __expf(Sv[5]) : 0.f;
            float p6 = (kb + 8 <= row1) ? __expf(Sv[6]) : 0.f;
            float p7 = (kb + 9 <= row1) ? __expf(Sv[7]) : 0.f;
            zs0 += p0 + p1 + p4 + p5;
            zs1 += p2 + p3 + p6 + p7;

            *(float2*)(arow0 + kb)     = make_float2(p0, p1);
            *(float2*)(arow1 + kb)     = make_float2(p2, p3);
            *(float2*)(arow0 + kb + 8) = make_float2(p4, p5);
            *(float2*)(arow1 + kb + 8) = make_float2(p6, p7);

            uint32_t Ph[4], Pl[4];
            split_pack(p0, p1, Ph[0], Pl[0]);
            split_pack(p2, p3, Ph[1], Pl[1]);
            split_pack(p4, p5, Ph[2], Pl[2]);
            split_pack(p6, p7, Ph[3], Pl[3]);

#pragma unroll
            for (int dd = 0; dd < 4; dd++) {
                uint32_t v0, v1, v2, v3;
                uint32_t off = (uint32_t)((np * 16 + key_l) * KPAD + (dd << 4) + d_l);
                ldsm4t(v0, v1, v2, v3, sptr(vh + off));
                mma16816(Ov[2 * dd],     Ph, v0, v1);
                mma16816(Ov[2 * dd],     Pl, v0, v1);
                mma16816(Ov[2 * dd + 1], Ph, v2, v3);
                mma16816(Ov[2 * dd + 1], Pl, v2, v3);
            }
        }
    }

    // reduce Z over the 4 lanes covering each row
    zs0 += __shfl_xor_sync(0xffffffffu, zs0, 1);
    zs0 += __shfl_xor_sync(0xffffffffu, zs0, 2);
    zs1 += __shfl_xor_sync(0xffffffffu, zs1, 1);
    zs1 += __shfl_xor_sync(0xffffffffu, zs1, 2);
    const float zi0 = 1.0f / zs0;
    const float zi1 = 1.0f / zs1;

    // write context, normalized
    {
        float* crow0 = ctx + ((size_t)bh * NS + row0) * ND;
        float* crow1 = ctx + ((size_t)bh * NS + row1) * ND;
#pragma unroll
        for (int dt = 0; dt < 8; dt++) {
            int c = (dt << 3) + (t4 << 1);
            *(float2*)(crow0 + c) = make_float2(Ov[dt][0] * zi0, Ov[dt][1] * zi0);
            *(float2*)(crow1 + c) = make_float2(Ov[dt][2] * zi1, Ov[dt][3] * zi1);
        }
    }

    // rescale the warp's 16 attn rows in place (reads mostly hit L2)
    __syncwarp();
    {
        const int ks = (qt + 1) << 7;       // causal band width for this q-tile
        const int n4 = ks >> 2;             // float4 per row
        float* wbase = attn + ((size_t)bh * NS + r0 + (w << 4)) * NS;
#pragma unroll 1
        for (int j = 0; j < 8; j++) {
            float za = __shfl_sync(0xffffffffu, zs0, j << 2);
            float zb = __shfl_sync(0xffffffffu, zs1, j << 2);
            float ra = 1.0f / za, rb = 1.0f / zb;
            float4* rowa = (float4*)(wbase + (size_t)j * NS);
            float4* rowb = (float4*)(wbase + (size_t)(j + 8) * NS);
            for (int c = L; c < n4; c += 32) {
                float4 v = rowa[c];
                v.x *= ra; v.y *= ra; v.z *= ra; v.w *= ra;
                rowa[c] = v;
                float4 u = rowb[c];
                u.x *= rb; u.y *= rb; u.z *= rb; u.w *= rb;
                rowb[c] = u;
            }
        }
    }

    // zero-fill masked region beyond the causal band
    {
        const int ks = (qt + 1) << 7;
        if (ks < NS) {
            const int width4 = (NS - ks) >> 2;
            float4 z4 = make_float4(0.f, 0.f, 0.f, 0.f);
            float* abase = attn + ((size_t)bh * NS + r0) * NS + ks;
            const int total = 128 * width4;
            for (int i = tid; i < total; i += 256) {
                int row = i / width4;
                int c = i - row * width4;
                ((float4*)(abase + (size_t)row * NS))[c] = z4;
            }
        }
    }
}

extern "C" void kernel_launch(void* const* d_in, const int* in_sizes, int n_in,
                              void* d_out, int out_size) {
    const float* Q = (const float*)d_in[0];
    const float* K = (const float*)d_in[1];
    const float* V = (const float*)d_in[2];
    float* ctx = (float*)d_out;
    float* attn = (float*)d_out + (size_t)NB * NH * NS * ND;

    static bool attr_set = false;
    if (!attr_set) {
        cudaFuncSetAttribute(attn_fused, cudaFuncAttributeMaxDynamicSharedMemorySize, 83968);
        attr_set = true;
    }

    dim3 grid(NB * NH, NS / 128);
    dim3 block(256);
    attn_fused<<<grid, block, 83968>>>(Q, K, V, ctx, attn);
}

// round 9
// speedup vs baseline: 1.5050x; 1.0870x over previous
#include <cuda_runtime.h>
#include <cuda_fp16.h>
#include <cstdint>
#include <cstddef>

#define NB 4
#define NH 16
#define NS 2048
#define ND 64
#define KPAD 72
#define STAGE_OFF 18432   // after 2 fp16 buffers of 64*KPAD*2 = 9216 B each

static __device__ __forceinline__ uint32_t sptr(const void* p) {
    return (uint32_t)__cvta_generic_to_shared(p);
}
static __device__ __forceinline__ void cpasync16(uint32_t dst, const void* src) {
    asm volatile("cp.async.cg.shared.global [%0], [%1], 16;" :: "r"(dst), "l"(src));
}
static __device__ __forceinline__ void ldsm4(uint32_t& r0, uint32_t& r1, uint32_t& r2, uint32_t& r3, uint32_t a) {
    asm volatile("ldmatrix.sync.aligned.m8n8.x4.shared.b16 {%0,%1,%2,%3},[%4];"
                 : "=r"(r0), "=r"(r1), "=r"(r2), "=r"(r3) : "r"(a));
}
static __device__ __forceinline__ void ldsm4t(uint32_t& r0, uint32_t& r1, uint32_t& r2, uint32_t& r3, uint32_t a) {
    asm volatile("ldmatrix.sync.aligned.m8n8.x4.trans.shared.b16 {%0,%1,%2,%3},[%4];"
                 : "=r"(r0), "=r"(r1), "=r"(r2), "=r"(r3) : "r"(a));
}
static __device__ __forceinline__ void mma16816(float* d, const uint32_t* a, uint32_t b0, uint32_t b1) {
    asm volatile(
        "mma.sync.aligned.m16n8k16.row.col.f32.f16.f16.f32 "
        "{%0,%1,%2,%3},{%4,%5,%6,%7},{%8,%9},{%0,%1,%2,%3};"
        : "+f"(d[0]), "+f"(d[1]), "+f"(d[2]), "+f"(d[3])
        : "r"(a[0]), "r"(a[1]), "r"(a[2]), "r"(a[3]), "r"(b0), "r"(b1));
}
// split pair of fp32 into fp16 hi + fp16 residual (packed half2 regs)
static __device__ __forceinline__ void split_pack(float a, float b, uint32_t& hi, uint32_t& lo) {
    __half ha = __float2half_rn(a);
    __half hb = __float2half_rn(b);
    float la = a - __half2float(ha);
    float lb = b - __half2float(hb);
    __half2 h = __halves2half2(ha, hb);
    __half2 l = __halves2half2(__float2half_rn(la), __float2half_rn(lb));
    hi = *(uint32_t*)&h;
    lo = *(uint32_t*)&l;
}
// fp32x4 -> fp16x4 store (hi only)
static __device__ __forceinline__ void h4store(__half* dst, float4 v) {
    __half2 a = __halves2half2(__float2half_rn(v.x), __float2half_rn(v.y));
    __half2 b = __halves2half2(__float2half_rn(v.z), __float2half_rn(v.w));
    ((__half2*)dst)[0] = a;
    ((__half2*)dst)[1] = b;
}

// Two-loop fused attention, fp16 2-term split: S=(Qh+Ql)Kh, O=(Ph+Pl)Vh.
// loop1: Z[row] = sum exp(s) (K staged only, no stores)
// loop2: recompute s, write P=exp(s)/Z once (normalized), accumulate O=P.V
// cp.async double-buffered staging. grid(64,16), block 256, 2 CTAs/SM.
__global__ __launch_bounds__(256, 2) void attn_fused(const float* __restrict__ Q,
                                                     const float* __restrict__ K,
                                                     const float* __restrict__ V,
                                                     float* __restrict__ ctx,
                                                     float* __restrict__ attn) {
    extern __shared__ char smem[];
    __half* kh = (__half*)smem;                    // 64 x KPAD
    __half* vh = kh + 64 * KPAD;                   // 64 x KPAD
    // two fp32 staging buffers of 32KB (K 16KB + V 16KB) at STAGE_OFF
    // qs (128x64 fp32, 32KB) overlays staging buffer 1; freed after A-frag build
    float* qs = (float*)(smem + STAGE_OFF + 32768);
    const uint32_t stage_base = sptr(smem + STAGE_OFF);

    const int bh = blockIdx.x;
    const int qt = (int)gridDim.y - 1 - (int)blockIdx.y;  // heavy tiles first
    const int r0 = qt << 7;
    const float* Qb = Q + ((size_t)bh * NS + r0) * ND;
    const float* Kb = K + (size_t)bh * NS * ND;
    const float* Vb = V + (size_t)bh * NS * ND;
    const int tid = threadIdx.x;
    const int nsteps = (r0 + 128) >> 6;

    // load Q (scaled) into qs; prefetch K tile 0 into staging buffer 0
    for (int i = tid; i < 2048; i += 256) {
        float4 v = ((const float4*)Qb)[i];
        v.x *= 0.125f; v.y *= 0.125f; v.z *= 0.125f; v.w *= 0.125f;
        ((float4*)qs)[i] = v;
    }
    {
        const float4* kg = (const float4*)Kb;
        for (int i = tid; i < 1024; i += 256)
            cpasync16(stage_base + i * 16, kg + i);
        asm volatile("cp.async.commit_group;");
    }
    __syncthreads();

    const int w = tid >> 5, L = tid & 31, g2 = L >> 2, t4 = L & 3, g3 = L >> 3, lr = L & 7;

    uint32_t Ah[4][4], Al[4][4];
    {
        const int rA = (w << 4) + g2;
#pragma unroll
        for (int kc = 0; kc < 4; kc++) {
            int c0 = (kc << 4) + (t4 << 1);
            split_pack(qs[rA * 64 + c0],           qs[rA * 64 + c0 + 1],           Ah[kc][0], Al[kc][0]);
            split_pack(qs[(rA + 8) * 64 + c0],     qs[(rA + 8) * 64 + c0 + 1],     Ah[kc][1], Al[kc][1]);
            split_pack(qs[rA * 64 + c0 + 8],       qs[rA * 64 + c0 + 9],           Ah[kc][2], Al[kc][2]);
            split_pack(qs[(rA + 8) * 64 + c0 + 8], qs[(rA + 8) * 64 + c0 + 9],     Ah[kc][3], Al[kc][3]);
        }
    }
    __syncthreads();  // qs consumed; staging buffer 1 may be overwritten

    const int row0 = r0 + (w << 4) + g2;
    const int row1 = row0 + 8;
    const int key_l = lr + ((g3 & 1) << 3);
    const int d_l = (g3 & 2) << 2;

    // ------------------ loop 1: Z only (K staged, no V, no stores) -----------
    float zs0 = 0.f, zs1 = 0.f;
    for (int s = 0; s < nsteps; s++) {
        if (s + 1 < nsteps) {
            const int k1 = (s + 1) << 6;
            const uint32_t sb = stage_base + ((s + 1) & 1) * 32768;
            const float4* kg = (const float4*)(Kb + (size_t)k1 * ND);
            for (int i = tid; i < 1024; i += 256)
                cpasync16(sb + i * 16, kg + i);
            asm volatile("cp.async.commit_group;");
            asm volatile("cp.async.wait_group 1;");
        } else {
            asm volatile("cp.async.wait_group 0;");
        }
        __syncthreads();

        {
            const float4* kf = (const float4*)(smem + STAGE_OFF + (s & 1) * 32768);
            for (int i = tid; i < 1024; i += 256) {
                int key = i >> 4, d = (i & 15) << 2;
                h4store(kh + key * KPAD + d, kf[i]);
            }
        }
        __syncthreads();

        const int k0 = s << 6;
#pragma unroll
        for (int np = 0; np < 4; np++) {
            float Sv[8] = {0.f, 0.f, 0.f, 0.f, 0.f, 0.f, 0.f, 0.f};
#pragma unroll
            for (int kc = 0; kc < 4; kc++) {
                uint32_t b0, b1, b2, b3;
                uint32_t off = (uint32_t)((np * 16 + key_l) * KPAD + (kc << 4) + d_l);
                ldsm4(b0, b1, b2, b3, sptr(kh + off));
                mma16816(Sv,     Ah[kc], b0, b2);
                mma16816(Sv,     Al[kc], b0, b2);
                mma16816(Sv + 4, Ah[kc], b1, b3);
                mma16816(Sv + 4, Al[kc], b1, b3);
            }
            const int kb = k0 + (np << 4) + (t4 << 1);
            float p;
            p = (kb     <= row0) ? __expf(Sv[0]) : 0.f; zs0 += p;
            p = (kb + 1 <= row0) ? __expf(Sv[1]) : 0.f; zs0 += p;
            p = (kb     <= row1) ? __expf(Sv[2]) : 0.f; zs1 += p;
            p = (kb + 1 <= row1) ? __expf(Sv[3]) : 0.f; zs1 += p;
            p = (kb + 8 <= row0) ? __expf(Sv[4]) : 0.f; zs0 += p;
            p = (kb + 9 <= row0) ? __expf(Sv[5]) : 0.f; zs0 += p;
            p = (kb + 8 <= row1) ? __expf(Sv[6]) : 0.f; zs1 += p;
            p = (kb + 9 <= row1) ? __expf(Sv[7]) : 0.f; zs1 += p;
        }
    }

    zs0 += __shfl_xor_sync(0xffffffffu, zs0, 1);
    zs0 += __shfl_xor_sync(0xffffffffu, zs0, 2);
    zs1 += __shfl_xor_sync(0xffffffffu, zs1, 1);
    zs1 += __shfl_xor_sync(0xffffffffu, zs1, 2);
    const float zi0 = 1.0f / zs0;
    const float zi1 = 1.0f / zs1;

    float* arow0 = attn + ((size_t)bh * NS + row0) * NS;
    float* arow1 = attn + ((size_t)bh * NS + row1) * NS;

    float Ov[8][4];
#pragma unroll
    for (int i = 0; i < 8; i++)
#pragma unroll
        for (int j = 0; j < 4; j++) Ov[i][j] = 0.f;

    // prefetch K+V tile 0 for loop 2
    {
        const float4* kg = (const float4*)Kb;
        const float4* vg = (const float4*)Vb;
        for (int i = tid; i < 1024; i += 256) {
            cpasync16(stage_base + i * 16, kg + i);
            cpasync16(stage_base + 16384 + i * 16, vg + i);
        }
        asm volatile("cp.async.commit_group;");
    }

    // ------------- loop 2: emit normalized P, accumulate O -------------------
    for (int s = 0; s < nsteps; s++) {
        if (s + 1 < nsteps) {
            const int k1 = (s + 1) << 6;
            const uint32_t sb = stage_base + ((s + 1) & 1) * 32768;
            const float4* kg = (const float4*)(Kb + (size_t)k1 * ND);
            const float4* vg = (const float4*)(Vb + (size_t)k1 * ND);
            for (int i = tid; i < 1024; i += 256) {
                cpasync16(sb + i * 16, kg + i);
                cpasync16(sb + 16384 + i * 16, vg + i);
            }
            asm volatile("cp.async.commit_group;");
            asm volatile("cp.async.wait_group 1;");
        } else {
            asm volatile("cp.async.wait_group 0;");
        }
        __syncthreads();

        {
            const float4* kf = (const float4*)(smem + STAGE_OFF + (s & 1) * 32768);
            const float4* vf = kf + 1024;
            for (int i = tid; i < 1024; i += 256) {
                int key = i >> 4, d = (i & 15) << 2;
                h4store(kh + key * KPAD + d, kf[i]);
                h4store(vh + key * KPAD + d, vf[i]);
            }
        }
        __syncthreads();

        const int k0 = s << 6;
#pragma unroll
        for (int np = 0; np < 4; np++) {
            float Sv[8] = {0.f, 0.f, 0.f, 0.f, 0.f, 0.f, 0.f, 0.f};
#pragma unroll
            for (int kc = 0; kc < 4; kc++) {
                uint32_t b0, b1, b2, b3;
                uint32_t off = (uint32_t)((np * 16 + key_l) * KPAD + (kc << 4) + d_l);
                ldsm4(b0, b1, b2, b3, sptr(kh + off));
                mma16816(Sv,     Ah[kc], b0, b2);
                mma16816(Sv,     Al[kc], b0, b2);
                mma16816(Sv + 4, Ah[kc], b1, b3);
                mma16816(Sv + 4, Al[kc], b1, b3);
            }
            const int kb = k0 + (np << 4) + (t4 << 1);
            // normalized probabilities
            float p0 = (kb     <= row0) ? __expf(Sv[0]) * zi0 : 0.f;
            float p1 = (kb + 1 <= row0) ? __expf(Sv[1]) * zi0 : 0.f;
            float p2 = (kb     <= row1) ? __expf(Sv[2]) * zi1 : 0.f;
            float p3 = (kb + 1 <= row1) ? __expf(Sv[3]) * zi1 : 0.f;
            float p4 = (kb + 8 <= row0) ? __expf(Sv[4]) * zi0 : 0.f;
            float p5 = (kb + 9 <= row0) ? __expf(Sv[5]) * zi0 : 0.f;
            float p6 = (kb + 8 <= row1) ? __expf(Sv[6]) * zi1 : 0.f;
            float p7 = (kb + 9 <= row1) ? __expf(Sv[7]) * zi1 : 0.f;

            *(float2*)(arow0 + kb)     = make_float2(p0, p1);
            *(float2*)(arow1 + kb)     = make_float2(p2, p3);
            *(float2*)(arow0 + kb + 8) = make_float2(p4, p5);
            *(float2*)(arow1 + kb + 8) = make_float2(p6, p7);

            uint32_t Ph[4], Pl[4];
            split_pack(p0, p1, Ph[0], Pl[0]);
            split_pack(p2, p3, Ph[1], Pl[1]);
            split_pack(p4, p5, Ph[2], Pl[2]);
            split_pack(p6, p7, Ph[3], Pl[3]);

#pragma unroll
            for (int dd = 0; dd < 4; dd++) {
                uint32_t v0, v1, v2, v3;
                uint32_t off = (uint32_t)((np * 16 + key_l) * KPAD + (dd << 4) + d_l);
                ldsm4t(v0, v1, v2, v3, sptr(vh + off));
                mma16816(Ov[2 * dd],     Ph, v0, v1);
                mma16816(Ov[2 * dd],     Pl, v0, v1);
                mma16816(Ov[2 * dd + 1], Ph, v2, v3);
                mma16816(Ov[2 * dd + 1], Pl, v2, v3);
            }
        }
    }

    // write context (P already normalized)
    {
        float* crow0 = ctx + ((size_t)bh * NS + row0) * ND;
        float* crow1 = ctx + ((size_t)bh * NS + row1) * ND;
#pragma unroll
        for (int dt = 0; dt < 8; dt++) {
            int c = (dt << 3) + (t4 << 1);
            *(float2*)(crow0 + c) = make_float2(Ov[dt][0], Ov[dt][1]);
            *(float2*)(crow1 + c) = make_float2(Ov[dt][2], Ov[dt][3]);
        }
    }

    // zero-fill masked region beyond the causal band
    {
        const int ks = (qt + 1) << 7;
        if (ks < NS) {
            const int width4 = (NS - ks) >> 2;
            float4 z4 = make_float4(0.f, 0.f, 0.f, 0.f);
            float* abase = attn + ((size_t)bh * NS + r0) * NS + ks;
            const int total = 128 * width4;
            for (int i = tid; i < total; i += 256) {
                int row = i / width4;
                int c = i - row * width4;
                ((float4*)(abase + (size_t)row * NS))[c] = z4;
            }
        }
    }
}

extern "C" void kernel_launch(void* const* d_in, const int* in_sizes, int n_in,
                              void* d_out, int out_size) {
    const float* Q = (const float*)d_in[0];
    const float* K = (const float*)d_in[1];
    const float* V = (const float*)d_in[2];
    float* ctx = (float*)d_out;
    float* attn = (float*)d_out + (size_t)NB * NH * NS * ND;

    static bool attr_set = false;
    if (!attr_set) {
        cudaFuncSetAttribute(attn_fused, cudaFuncAttributeMaxDynamicSharedMemorySize, 83968);
        attr_set = true;
    }

    dim3 grid(NB * NH, NS / 128);
    dim3 block(256);
    attn_fused<<<grid, block, 83968>>>(Q, K, V, ctx, attn);
}

// round 12
// speedup vs baseline: 1.9022x; 1.2639x over previous
#include <cuda_runtime.h>
#include <cuda_fp16.h>
#include <cstdint>
#include <cstddef>

#define NB 4
#define NH 16
#define NS 2048
#define ND 64
#define KPAD 72
#define STAGE_OFF 18432   // after 2 fp16 buffers of 64*KPAD*2 = 9216 B each

static __device__ __forceinline__ uint32_t sptr(const void* p) {
    return (uint32_t)__cvta_generic_to_shared(p);
}
static __device__ __forceinline__ void cpasync16(uint32_t dst, const void* src) {
    asm volatile("cp.async.cg.shared.global [%0], [%1], 16;" :: "r"(dst), "l"(src));
}
static __device__ __forceinline__ void ldsm4(uint32_t& r0, uint32_t& r1, uint32_t& r2, uint32_t& r3, uint32_t a) {
    asm volatile("ldmatrix.sync.aligned.m8n8.x4.shared.b16 {%0,%1,%2,%3},[%4];"
                 : "=r"(r0), "=r"(r1), "=r"(r2), "=r"(r3) : "r"(a));
}
static __device__ __forceinline__ void ldsm4t(uint32_t& r0, uint32_t& r1, uint32_t& r2, uint32_t& r3, uint32_t a) {
    asm volatile("ldmatrix.sync.aligned.m8n8.x4.trans.shared.b16 {%0,%1,%2,%3},[%4];"
                 : "=r"(r0), "=r"(r1), "=r"(r2), "=r"(r3) : "r"(a));
}
static __device__ __forceinline__ void mma16816(float* d, const uint32_t* a, uint32_t b0, uint32_t b1) {
    asm volatile(
        "mma.sync.aligned.m16n8k16.row.col.f32.f16.f16.f32 "
        "{%0,%1,%2,%3},{%4,%5,%6,%7},{%8,%9},{%0,%1,%2,%3};"
        : "+f"(d[0]), "+f"(d[1]), "+f"(d[2]), "+f"(d[3])
        : "r"(a[0]), "r"(a[1]), "r"(a[2]), "r"(a[3]), "r"(b0), "r"(b1));
}
static __device__ __forceinline__ uint32_t pack2(float a, float b) {
    __half2 h = __halves2half2(__float2half_rn(a), __float2half_rn(b));
    return *(uint32_t*)&h;
}
// fp32x4 -> fp16x4 store
static __device__ __forceinline__ void h4store(__half* dst, float4 v) {
    __half2 a = __halves2half2(__float2half_rn(v.x), __float2half_rn(v.y));
    __half2 b = __halves2half2(__float2half_rn(v.z), __float2half_rn(v.w));
    ((__half2*)dst)[0] = a;
    ((__half2*)dst)[1] = b;
}

// Two-loop fused attention, plain fp16 operands, fp32 accumulate:
// loop1: Z[row] = sum exp(s) (K staged only, no stores)
// loop2: recompute s, write P=exp(s)/Z once (normalized), accumulate O=P.V
// cp.async double-buffered staging. grid(64,16), block 256, 2 CTAs/SM.
__global__ __launch_bounds__(256, 2) void attn_fused(const float* __restrict__ Q,
                                                     const float* __restrict__ K,
                                                     const float* __restrict__ V,
                                                     float* __restrict__ ctx,
                                                     float* __restrict__ attn) {
    extern __shared__ char smem[];
    __half* kh = (__half*)smem;                    // 64 x KPAD
    __half* vh = kh + 64 * KPAD;                   // 64 x KPAD
    // two fp32 staging buffers of 32KB (K 16KB + V 16KB) at STAGE_OFF
    // qs (128x64 fp32, 32KB) overlays staging buffer 1; freed after A-frag build
    float* qs = (float*)(smem + STAGE_OFF + 32768);
    const uint32_t stage_base = sptr(smem + STAGE_OFF);

    const int bh = blockIdx.x;
    const int qt = (int)gridDim.y - 1 - (int)blockIdx.y;  // heavy tiles first
    const int r0 = qt << 7;
    const float* Qb = Q + ((size_t)bh * NS + r0) * ND;
    const float* Kb = K + (size_t)bh * NS * ND;
    const float* Vb = V + (size_t)bh * NS * ND;
    const int tid = threadIdx.x;
    const int nsteps = (r0 + 128) >> 6;

    // load Q (scaled) into qs; prefetch K tile 0 into staging buffer 0
    for (int i = tid; i < 2048; i += 256) {
        float4 v = ((const float4*)Qb)[i];
        v.x *= 0.125f; v.y *= 0.125f; v.z *= 0.125f; v.w *= 0.125f;
        ((float4*)qs)[i] = v;
    }
    {
        const float4* kg = (const float4*)Kb;
        for (int i = tid; i < 1024; i += 256)
            cpasync16(stage_base + i * 16, kg + i);
        asm volatile("cp.async.commit_group;");
    }
    __syncthreads();

    const int w = tid >> 5, L = tid & 31, g2 = L >> 2, t4 = L & 3, g3 = L >> 3, lr = L & 7;

    uint32_t Ah[4][4];
    {
        const int rA = (w << 4) + g2;
#pragma unroll
        for (int kc = 0; kc < 4; kc++) {
            int c0 = (kc << 4) + (t4 << 1);
            Ah[kc][0] = pack2(qs[rA * 64 + c0],           qs[rA * 64 + c0 + 1]);
            Ah[kc][1] = pack2(qs[(rA + 8) * 64 + c0],     qs[(rA + 8) * 64 + c0 + 1]);
            Ah[kc][2] = pack2(qs[rA * 64 + c0 + 8],       qs[rA * 64 + c0 + 9]);
            Ah[kc][3] = pack2(qs[(rA + 8) * 64 + c0 + 8], qs[(rA + 8) * 64 + c0 + 9]);
        }
    }
    __syncthreads();  // qs consumed; staging buffer 1 may be overwritten

    const int row0 = r0 + (w << 4) + g2;
    const int row1 = row0 + 8;
    const int key_l = lr + ((g3 & 1) << 3);
    const int d_l = (g3 & 2) << 2;

    // ------------------ loop 1: Z only (K staged, no V, no stores) -----------
    float zs0 = 0.f, zs1 = 0.f;
    for (int s = 0; s < nsteps; s++) {
        if (s + 1 < nsteps) {
            const int k1 = (s + 1) << 6;
            const uint32_t sb = stage_base + ((s + 1) & 1) * 32768;
            const float4* kg = (const float4*)(Kb + (size_t)k1 * ND);
            for (int i = tid; i < 1024; i += 256)
                cpasync16(sb + i * 16, kg + i);
            asm volatile("cp.async.commit_group;");
            asm volatile("cp.async.wait_group 1;");
        } else {
            asm volatile("cp.async.wait_group 0;");
        }
        __syncthreads();

        {
            const float4* kf = (const float4*)(smem + STAGE_OFF + (s & 1) * 32768);
            for (int i = tid; i < 1024; i += 256) {
                int key = i >> 4, d = (i & 15) << 2;
                h4store(kh + key * KPAD + d, kf[i]);
            }
        }
        __syncthreads();

        const int k0 = s << 6;
#pragma unroll
        for (int np = 0; np < 4; np++) {
            float Sv[8] = {0.f, 0.f, 0.f, 0.f, 0.f, 0.f, 0.f, 0.f};
#pragma unroll
            for (int kc = 0; kc < 4; kc++) {
                uint32_t b0, b1, b2, b3;
                uint32_t off = (uint32_t)((np * 16 + key_l) * KPAD + (kc << 4) + d_l);
                ldsm4(b0, b1, b2, b3, sptr(kh + off));
                mma16816(Sv,     Ah[kc], b0, b2);
                mma16816(Sv + 4, Ah[kc], b1, b3);
            }
            const int kb = k0 + (np << 4) + (t4 << 1);
            if (kb + 9 <= row0) {  // whole group visible for both rows
                zs0 += __expf(Sv[0]) + __expf(Sv[1]) + __expf(Sv[4]) + __expf(Sv[5]);
                zs1 += __expf(Sv[2]) + __expf(Sv[3]) + __expf(Sv[6]) + __expf(Sv[7]);
            } else {
                float p;
                p = (kb     <= row0) ? __expf(Sv[0]) : 0.f; zs0 += p;
                p = (kb + 1 <= row0) ? __expf(Sv[1]) : 0.f; zs0 += p;
                p = (kb     <= row1) ? __expf(Sv[2]) : 0.f; zs1 += p;
                p = (kb + 1 <= row1) ? __expf(Sv[3]) : 0.f; zs1 += p;
                p = (kb + 8 <= row0) ? __expf(Sv[4]) : 0.f; zs0 += p;
                p = (kb + 9 <= row0) ? __expf(Sv[5]) : 0.f; zs0 += p;
                p = (kb + 8 <= row1) ? __expf(Sv[6]) : 0.f; zs1 += p;
                p = (kb + 9 <= row1) ? __expf(Sv[7]) : 0.f; zs1 += p;
            }
        }
    }

    zs0 += __shfl_xor_sync(0xffffffffu, zs0, 1);
    zs0 += __shfl_xor_sync(0xffffffffu, zs0, 2);
    zs1 += __shfl_xor_sync(0xffffffffu, zs1, 1);
    zs1 += __shfl_xor_sync(0xffffffffu, zs1, 2);
    const float zi0 = 1.0f / zs0;
    const float zi1 = 1.0f / zs1;

    float* arow0 = attn + ((size_t)bh * NS + row0) * NS;
    float* arow1 = attn + ((size_t)bh * NS + row1) * NS;

    float Ov[8][4];
#pragma unroll
    for (int i = 0; i < 8; i++)
#pragma unroll
        for (int j = 0; j < 4; j++) Ov[i][j] = 0.f;

    // prefetch K+V tile 0 for loop 2
    {
        const float4* kg = (const float4*)Kb;
        const float4* vg = (const float4*)Vb;
        for (int i = tid; i < 1024; i += 256) {
            cpasync16(stage_base + i * 16, kg + i);
            cpasync16(stage_base + 16384 + i * 16, vg + i);
        }
        asm volatile("cp.async.commit_group;");
    }

    // ------------- loop 2: emit normalized P, accumulate O -------------------
    for (int s = 0; s < nsteps; s++) {
        if (s + 1 < nsteps) {
            const int k1 = (s + 1) << 6;
            const uint32_t sb = stage_base + ((s + 1) & 1) * 32768;
            const float4* kg = (const float4*)(Kb + (size_t)k1 * ND);
            const float4* vg = (const float4*)(Vb + (size_t)k1 * ND);
            for (int i = tid; i < 1024; i += 256) {
                cpasync16(sb + i * 16, kg + i);
                cpasync16(sb + 16384 + i * 16, vg + i);
            }
            asm volatile("cp.async.commit_group;");
            asm volatile("cp.async.wait_group 1;");
        } else {
            asm volatile("cp.async.wait_group 0;");
        }
        __syncthreads();

        {
            const float4* kf = (const float4*)(smem + STAGE_OFF + (s & 1) * 32768);
            const float4* vf = kf + 1024;
            for (int i = tid; i < 1024; i += 256) {
                int key = i >> 4, d = (i & 15) << 2;
                h4store(kh + key * KPAD + d, kf[i]);
                h4store(vh + key * KPAD + d, vf[i]);
            }
        }
        __syncthreads();

        const int k0 = s << 6;
#pragma unroll
        for (int np = 0; np < 4; np++) {
            float Sv[8] = {0.f, 0.f, 0.f, 0.f, 0.f, 0.f, 0.f, 0.f};
#pragma unroll
            for (int kc = 0; kc < 4; kc++) {
                uint32_t b0, b1, b2, b3;
                uint32_t off = (uint32_t)((np * 16 + key_l) * KPAD + (kc << 4) + d_l);
                ldsm4(b0, b1, b2, b3, sptr(kh + off));
                mma16816(Sv,     Ah[kc], b0, b2);
                mma16816(Sv + 4, Ah[kc], b1, b3);
            }
            const int kb = k0 + (np << 4) + (t4 << 1);
            float p0, p1, p2, p3, p4, p5, p6, p7;
            if (kb + 9 <= row0) {  // fully visible group
                p0 = __expf(Sv[0]) * zi0;
                p1 = __expf(Sv[1]) * zi0;
                p2 = __expf(Sv[2]) * zi1;
                p3 = __expf(Sv[3]) * zi1;
                p4 = __expf(Sv[4]) * zi0;
                p5 = __expf(Sv[5]) * zi0;
                p6 = __expf(Sv[6]) * zi1;
                p7 = __expf(Sv[7]) * zi1;
            } else {
                p0 = (kb     <= row0) ? __expf(Sv[0]) * zi0 : 0.f;
                p1 = (kb + 1 <= row0) ? __expf(Sv[1]) * zi0 : 0.f;
                p2 = (kb     <= row1) ? __expf(Sv[2]) * zi1 : 0.f;
                p3 = (kb + 1 <= row1) ? __expf(Sv[3]) * zi1 : 0.f;
                p4 = (kb + 8 <= row0) ? __expf(Sv[4]) * zi0 : 0.f;
                p5 = (kb + 9 <= row0) ? __expf(Sv[5]) * zi0 : 0.f;
                p6 = (kb + 8 <= row1) ? __expf(Sv[6]) * zi1 : 0.f;
                p7 = (kb + 9 <= row1) ? __expf(Sv[7]) * zi1 : 0.f;
            }

            *(float2*)(arow0 + kb)     = make_float2(p0, p1);
            *(float2*)(arow1 + kb)     = make_float2(p2, p3);
            *(float2*)(arow0 + kb + 8) = make_float2(p4, p5);
            *(float2*)(arow1 + kb + 8) = make_float2(p6, p7);

            uint32_t Ph[4];
            Ph[0] = pack2(p0, p1);
            Ph[1] = pack2(p2, p3);
            Ph[2] = pack2(p4, p5);
            Ph[3] = pack2(p6, p7);

#pragma unroll
            for (int dd = 0; dd < 4; dd++) {
                uint32_t v0, v1, v2, v3;
                uint32_t off = (uint32_t)((np * 16 + key_l) * KPAD + (dd << 4) + d_l);
                ldsm4t(v0, v1, v2, v3, sptr(vh + off));
                mma16816(Ov[2 * dd],     Ph, v0, v1);
                mma16816(Ov[2 * dd + 1], Ph, v2, v3);
            }
        }
    }

    // write context (P already normalized)
    {
        float* crow0 = ctx + ((size_t)bh * NS + row0) * ND;
        float* crow1 = ctx + ((size_t)bh * NS + row1) * ND;
#pragma unroll
        for (int dt = 0; dt < 8; dt++) {
            int c = (dt << 3) + (t4 << 1);
            *(float2*)(crow0 + c) = make_float2(Ov[dt][0], Ov[dt][1]);
            *(float2*)(crow1 + c) = make_float2(Ov[dt][2], Ov[dt][3]);
        }
    }

    // zero-fill masked region beyond the causal band
    {
        const int ks = (qt + 1) << 7;
        if (ks < NS) {
            const int width4 = (NS - ks) >> 2;
            float4 z4 = make_float4(0.f, 0.f, 0.f, 0.f);
            float* abase = attn + ((size_t)bh * NS + r0) * NS + ks;
            const int total = 128 * width4;
            for (int i = tid; i < total; i += 256) {
                int row = i / width4;
                int c = i - row * width4;
                ((float4*)(abase + (size_t)row * NS))[c] = z4;
            }
        }
    }
}

extern "C" void kernel_launch(void* const* d_in, const int* in_sizes, int n_in,
                              void* d_out, int out_size) {
    const float* Q = (const float*)d_in[0];
    const float* K = (const float*)d_in[1];
    const float* V = (const float*)d_in[2];
    float* ctx = (float*)d_out;
    float* attn = (float*)d_out + (size_t)NB * NH * NS * ND;

    static bool attr_set = false;
    if (!attr_set) {
        cudaFuncSetAttribute(attn_fused, cudaFuncAttributeMaxDynamicSharedMemorySize, 83968);
        attr_set = true;
    }

    dim3 grid(NB * NH, NS / 128);
    dim3 block(256);
    attn_fused<<<grid, block, 83968>>>(Q, K, V, ctx, attn);
}